// round 12
// baseline (speedup 1.0000x reference)
#include <cuda_runtime.h>
#include <cstdint>

#define M 8192
#define NW 128          // 64-bit words per row (M/64)
#define NMS_T 0.3f
#define CH 256          // scan chunk size (elements)
#define WPC 4           // words per chunk (CH/64)
#define TILE 2048       // sort tile size
#define NTILE 4         // number of sort tiles (M/TILE)

typedef unsigned long long u64;

// ---------------- device scratch (no runtime allocation allowed) ------------
__device__ float  g_d[M * 5];        // transformed detections (orig order)
__device__ u64    g_ckey[M];         // packed (key<<13 | idx), padded to 8192
__device__ int    g_cnt;             // valid count (atomic; reset by scan)
__device__ int    g_V;               // valid count (published by lsort)
__device__ float  g_ds[M * 5];       // sorted detections (first V rows)
__device__ float4 g_boxes[M];        // x1,y1,x2,y2 (sorted order, first V)
__device__ u64    g_mask[M * NW];    // suppression bitmask (i>j bits only)

// ---------------- kernel 1: transform + score + compact (coalesced) ---------
__global__ void __launch_bounds__(256)
prep_kernel(const float* __restrict__ det, const float* __restrict__ off,
            const float* __restrict__ scl, const float* __restrict__ bnd) {
    __shared__ float srow[256 * 5];
    int b = blockIdx.x;                    // 32 blocks x 256 rows
    int tid = threadIdx.x;
    int lane = tid & 31;
    const float* src = det + b * 256 * 5;
    for (int i = tid; i < 256 * 5; i += 256) srow[i] = src[i];
    __syncthreads();

    int i = b * 256 + tid;                 // global row
    int w = i >> 10;
    float a0 = srow[tid * 5 + 0], a1 = srow[tid * 5 + 1], a2 = srow[tid * 5 + 2];
    float a3 = srow[tid * 5 + 3], a4 = srow[tid * 5 + 4];
    float d0 = off[w * 5 + 0] + a0 * scl[w * 5 + 0];
    float d1 = off[w * 5 + 1] + a1 * scl[w * 5 + 1];
    float d2 = off[w * 5 + 2] + a2 * scl[w * 5 + 2];
    float d3 = off[w * 5 + 3] + a3 * scl[w * 5 + 3];
    float d4 = off[w * 5 + 4] + a4 * scl[w * 5 + 4];
    bool valid = (a1 < bnd[w * 4 + 1]) && (a1 > bnd[w * 4 + 0]) &&
                 (a2 < bnd[w * 4 + 3]) && (a2 > bnd[w * 4 + 2]);

    g_d[i * 5 + 0] = d0;
    g_d[i * 5 + 1] = d1;
    g_d[i * 5 + 2] = d2;
    g_d[i * 5 + 3] = d3;
    g_d[i * 5 + 4] = d4;

    bool take = valid && d0 > 0.0f;        // non-positive scores -> zero rows
    unsigned ball = __ballot_sync(0xffffffffu, take);
    if (ball) {
        int nb = __popc(ball);
        int leader = __ffs(ball) - 1;
        int base = 0;
        if (lane == leader) base = atomicAdd(&g_cnt, nb);
        base = __shfl_sync(0xffffffffu, base, leader);
        if (take) {
            int o = __popc(ball & ((1u << lane) - 1));
            unsigned key = ~(__float_as_uint(d0) | 0x80000000u);
            g_ckey[base + o] = ((u64)key << 13) | (u64)i;  // (score desc, idx asc)
        }
    }
}

// ---------------- kernel 2a: local bitonic sort of 2048-tiles ---------------
__global__ void __launch_bounds__(1024) lsort_kernel() {
    __shared__ u64 sv[TILE];
    int tb = blockIdx.x << 11;
    int tid = threadIdx.x;
    int V = g_cnt;
    if (tb == 0 && tid == 0) g_V = V;

    if (tb >= V) {                         // pure padding tile: just materialize
        g_ckey[tb + tid] = ~0ull;
        g_ckey[tb + tid + 1024] = ~0ull;
        return;
    }

    u64 r0 = (tb + tid < V) ? g_ckey[tb + tid] : ~0ull;
    u64 r1 = (tb + tid + 1024 < V) ? g_ckey[tb + tid + 1024] : ~0ull;

    // phase A: k = 2..32 entirely in registers (intra-warp shuffles)
    int e0 = tb + tid, e1 = tb + 1024 + tid;
#pragma unroll
    for (int k = 2; k <= 32; k <<= 1) {
#pragma unroll
        for (int s = k >> 1; s >= 1; s >>= 1) {
            u64 o0 = __shfl_xor_sync(0xffffffffu, r0, s);
            u64 o1 = __shfl_xor_sync(0xffffffffu, r1, s);
            bool m0 = (((e0 & s) == 0) == ((e0 & k) == 0));
            bool m1 = (((e1 & s) == 0) == ((e1 & k) == 0));
            r0 = ((r0 < o0) == m0) ? r0 : o0;
            r1 = ((r1 < o1) == m1) ? r1 : o1;
        }
    }
    sv[tid] = r0;
    sv[tid + 1024] = r1;
    __syncthreads();

    // phase B: k = 64..2048 (strides >=32 in smem, <=16 via shuffles)
#pragma unroll
    for (int k = 64; k <= TILE; k <<= 1) {
        for (int s = k >> 1; s >= 32; s >>= 1) {
            int a = ((tid & ~(s - 1)) << 1) | (tid & (s - 1));
            bool up = (((tb + a) & k) == 0);
            u64 x = sv[a], y = sv[a + s];
            if ((x > y) == up) { sv[a] = y; sv[a + s] = x; }
            __syncthreads();
        }
        r0 = sv[tid];
        r1 = sv[tid + 1024];
#pragma unroll
        for (int s = 16; s >= 1; s >>= 1) {
            u64 o0 = __shfl_xor_sync(0xffffffffu, r0, s);
            u64 o1 = __shfl_xor_sync(0xffffffffu, r1, s);
            bool m0 = (((e0 & s) == 0) == ((e0 & k) == 0));
            bool m1 = (((e1 & s) == 0) == ((e1 & k) == 0));
            r0 = ((r0 < o0) == m0) ? r0 : o0;
            r1 = ((r1 < o1) == m1) ? r1 : o1;
        }
        if (k < TILE) {
            sv[tid] = r0;
            sv[tid + 1024] = r1;
            __syncthreads();
        }
    }
    g_ckey[tb + tid] = r0;
    g_ckey[tb + 1024 + tid] = r1;
}

// ---------------- kernel 2b: global compare-exchange stage ------------------
__global__ void __launch_bounds__(512) gmerge_kernel(int k, int s) {
    int v = blockIdx.x * 512 + threadIdx.x;       // 4096 pairs
    int a = ((v & ~(s - 1)) << 1) | (v & (s - 1));
    int b = a + s;
    bool up = ((a & k) == 0);
    u64 x = g_ckey[a], y = g_ckey[b];
    if ((x > y) == up) { g_ckey[a] = y; g_ckey[b] = x; }
}

// ---------------- kernel 2c: intra-tile merge (strides <=1024) --------------
template <int K, bool FINAL>
__global__ void __launch_bounds__(1024) lmerge_kernel() {
    __shared__ u64 sv[TILE];
    int tb = blockIdx.x << 11;
    int tid = threadIdx.x;
    sv[tid] = g_ckey[tb + tid];
    sv[tid + 1024] = g_ckey[tb + tid + 1024];
    __syncthreads();

    for (int s = 1024; s >= 32; s >>= 1) {
        int a = ((tid & ~(s - 1)) << 1) | (tid & (s - 1));
        bool up = (((tb + a) & K) == 0);
        u64 x = sv[a], y = sv[a + s];
        if ((x > y) == up) { sv[a] = y; sv[a + s] = x; }
        __syncthreads();
    }
    u64 r0 = sv[tid], r1 = sv[tid + 1024];
    int e0 = tb + tid, e1 = tb + 1024 + tid;
#pragma unroll
    for (int s = 16; s >= 1; s >>= 1) {
        u64 o0 = __shfl_xor_sync(0xffffffffu, r0, s);
        u64 o1 = __shfl_xor_sync(0xffffffffu, r1, s);
        bool m0 = (((e0 & s) == 0) == ((e0 & K) == 0));
        bool m1 = (((e1 & s) == 0) == ((e1 & K) == 0));
        r0 = ((r0 < o0) == m0) ? r0 : o0;
        r1 = ((r1 < o1) == m1) ? r1 : o1;
    }

    if (FINAL) {
        sv[tid] = r0;
        sv[tid + 1024] = r1;
        __syncthreads();
        // fused gather: build sorted rows + boxes for this tile
        int V = g_V;
        for (int l = tid; l < TILE; l += 1024) {
            int j = tb + l;
            if (j < V) {
                int idx = (int)(sv[l] & 0x1FFFu);
                float dd[5];
#pragma unroll
                for (int c = 0; c < 5; c++) {
                    dd[c] = g_d[idx * 5 + c];
                    g_ds[j * 5 + c] = dd[c];
                }
                g_boxes[j] = make_float4(dd[1] - 0.5f * dd[3], dd[2] - 0.5f * dd[4],
                                         dd[1] + 0.5f * dd[3], dd[2] + 0.5f * dd[4]);
            }
        }
    } else {
        g_ckey[tb + tid] = r0;
        g_ckey[tb + 1024 + tid] = r1;
    }
}

// ---------------- kernel 3: IoU bitmask (256 rows x 64 cols per block) ------
__global__ void __launch_bounds__(256) mask_kernel() {
    int bx = blockIdx.x;                       // column word 0..127
    int by = blockIdx.y;                       // row tile 0..31 (256 rows each)
    int V = g_V;
    if ((by << 8) >= V || (bx << 6) >= V) return;
    if (bx < (by << 2)) return;                // tile entirely i <= j

    __shared__ float4 cbox[64];
    __shared__ float  carea[64];
    int t = threadIdx.x;
    if (t < 64) {
        int ci = (bx << 6) + t;
        float4 cb = (ci < V) ? g_boxes[ci] : make_float4(0.f, 0.f, 0.f, 0.f);
        cbox[t] = cb;
        carea[t] = fmaxf(cb.z - cb.x, 0.f) * fmaxf(cb.w - cb.y, 0.f);
    }
    __syncthreads();

    int j = (by << 8) + t;
    if (j >= V) return;
    float4 rb = g_boxes[j];
    float  ra = fmaxf(rb.z - rb.x, 0.f) * fmaxf(rb.w - rb.y, 0.f);

    u64 bits = 0ull;
#pragma unroll
    for (int b = 0; b < 64; b++) {
        int i = (bx << 6) + b;
        if (i > j) {
            float iw = fmaxf(fminf(rb.z, cbox[b].z) - fmaxf(rb.x, cbox[b].x), 0.f);
            float ih = fmaxf(fminf(rb.w, cbox[b].w) - fmaxf(rb.y, cbox[b].y), 0.f);
            float inter = iw * ih;
            float uni = ra + carea[b] - inter;
            if (inter > NMS_T * fmaxf(uni, 1e-9f)) bits |= (1ull << b);
        }
    }
    g_mask[(size_t)j * NW + bx] = bits;
}

// helpers for the batched greedy (pure register selects, no arrays)
__device__ __forceinline__ int first_alive(u64 a0, u64 a1, u64 a2, u64 a3) {
    if (a0) return __ffsll((long long)a0) - 1;
    if (a1) return 64 + __ffsll((long long)a1) - 1;
    if (a2) return 128 + __ffsll((long long)a2) - 1;
    if (a3) return 192 + __ffsll((long long)a3) - 1;
    return -1;
}
__device__ __forceinline__ u64 sel_word(int r, u64 a0, u64 a1, u64 a2, u64 a3) {
    u64 x = (r < 64) ? a0 : (r < 128) ? a1 : (r < 192) ? a2 : a3;
    return x;
}
#define CLR_BIT(r, a0, a1, a2, a3) do {                 \
    u64 _m = 1ull << ((r) & 63);                        \
    if ((r) < 64) a0 &= ~_m;                            \
    else if ((r) < 128) a1 &= ~_m;                      \
    else if ((r) < 192) a2 &= ~_m;                      \
    else a3 &= ~_m; } while (0)
#define SET_BIT(r, a0, a1, a2, a3) do {                 \
    u64 _m = 1ull << ((r) & 63);                        \
    if ((r) < 64) a0 |= _m;                             \
    else if ((r) < 128) a1 |= _m;                       \
    else if ((r) < 192) a2 |= _m;                       \
    else a3 |= _m; } while (0)

// ---------------- kernel 4: greedy NMS scan (3-deep batch) + fused output ---
__global__ void __launch_bounds__(512) scan_kernel(float* __restrict__ out) {
    __shared__ u64 remv[NW];
    __shared__ u64 skeep[NW];
    __shared__ u64 sdiag[CH][WPC];        // 8KB diagonal block
    __shared__ u64 part[512];
    __shared__ unsigned short klist[CH];
    __shared__ int knum;
    int t = threadIdx.x;
    int V = g_V;
    int NC = (V + CH - 1) / CH;
    int NWv = (V + 63) >> 6;

    if (t == 511) g_cnt = 0;              // deterministic reset for next replay
    if (t < NW) { remv[t] = 0ull; skeep[t] = 0ull; }
    part[t] = 0ull;

    // prefetch diag block of chunk 0 (row = i>>2, word = i&3)
    u64 d0 = 0ull, d1 = 0ull;
    if (NC > 0) {
        d0 = g_mask[(size_t)(t >> 2) * NW + (t & 3)];
        d1 = g_mask[(size_t)((t + 512) >> 2) * NW + ((t + 512) & 3)];
    }
    __syncthreads();

    for (int c = 0; c < NC; c++) {
        sdiag[t >> 2][t & 3] = d0;
        sdiag[(t + 512) >> 2][(t + 512) & 3] = d1;
        // fold prev chunk's propagation partials into remv (word c*WPC + t)
        if (t < NW) {
            int w = c * WPC + t;
            if (w < NW)
                remv[w] |= (part[t * 4] | part[t * 4 + 1]) |
                           (part[t * 4 + 2] | part[t * 4 + 3]);
        }
        __syncthreads();

        // prefetch next chunk's diag block
        if (c + 1 < NC) {
            int base = (c + 1) * CH;
            d0 = g_mask[(size_t)(base + (t >> 2)) * NW + ((c + 1) * WPC + (t & 3))];
            d1 = g_mask[(size_t)(base + ((t + 512) >> 2)) * NW +
                        ((c + 1) * WPC + ((t + 512) & 3))];
        }

        if (t == 0) {
            // batched 3-deep greedy, all state in explicit scalars
            u64 va0, va1, va2, va3, k0 = 0, k1 = 0, k2 = 0, k3 = 0;
            {
                int rb0 = V - ((c * WPC + 0) << 6);
                int rb1 = V - ((c * WPC + 1) << 6);
                int rb2 = V - ((c * WPC + 2) << 6);
                int rb3 = V - ((c * WPC + 3) << 6);
                u64 m0 = (rb0 >= 64) ? ~0ull : (rb0 <= 0 ? 0ull : ((1ull << rb0) - 1ull));
                u64 m1 = (rb1 >= 64) ? ~0ull : (rb1 <= 0 ? 0ull : ((1ull << rb1) - 1ull));
                u64 m2 = (rb2 >= 64) ? ~0ull : (rb2 <= 0 ? 0ull : ((1ull << rb2) - 1ull));
                u64 m3 = (rb3 >= 64) ? ~0ull : (rb3 <= 0 ? 0ull : ((1ull << rb3) - 1ull));
                va0 = ~remv[c * WPC + 0] & m0;
                va1 = ~remv[c * WPC + 1] & m1;
                va2 = ~remv[c * WPC + 2] & m2;
                va3 = ~remv[c * WPC + 3] & m3;
            }
            int n = 0;
            while (true) {
                int r1 = first_alive(va0, va1, va2, va3);
                if (r1 < 0) break;
                // candidates r2, r3 (next alive after clearing earlier)
                u64 ta0 = va0, ta1 = va1, ta2 = va2, ta3 = va3;
                CLR_BIT(r1, ta0, ta1, ta2, ta3);
                int r2 = first_alive(ta0, ta1, ta2, ta3);
                int r3 = -1;
                if (r2 >= 0) {
                    CLR_BIT(r2, ta0, ta1, ta2, ta3);
                    r3 = first_alive(ta0, ta1, ta2, ta3);
                }
                // issue all row loads up front (independent LDS, one latency)
                u64 w10 = sdiag[r1][0], w11 = sdiag[r1][1],
                    w12 = sdiag[r1][2], w13 = sdiag[r1][3];
                int r2c = (r2 >= 0) ? r2 : r1;
                u64 w20 = sdiag[r2c][0], w21 = sdiag[r2c][1],
                    w22 = sdiag[r2c][2], w23 = sdiag[r2c][3];
                int r3c = (r3 >= 0) ? r3 : r1;
                u64 w30 = sdiag[r3c][0], w31 = sdiag[r3c][1],
                    w32 = sdiag[r3c][2], w33 = sdiag[r3c][3];

                // commit r1
                klist[n++] = (unsigned short)r1;
                SET_BIT(r1, k0, k1, k2, k3);
                va0 &= ~w10; va1 &= ~w11; va2 &= ~w12; va3 &= ~w13;
                CLR_BIT(r1, va0, va1, va2, va3);

                // commit r2 iff it survived row1
                if (r2 >= 0 && ((sel_word(r2, va0, va1, va2, va3) >> (r2 & 63)) & 1ull)) {
                    klist[n++] = (unsigned short)r2;
                    SET_BIT(r2, k0, k1, k2, k3);
                    va0 &= ~w20; va1 &= ~w21; va2 &= ~w22; va3 &= ~w23;
                    CLR_BIT(r2, va0, va1, va2, va3);

                    // commit r3 iff it survived row1|row2
                    if (r3 >= 0 && ((sel_word(r3, va0, va1, va2, va3) >> (r3 & 63)) & 1ull)) {
                        klist[n++] = (unsigned short)r3;
                        SET_BIT(r3, k0, k1, k2, k3);
                        va0 &= ~w30; va1 &= ~w31; va2 &= ~w32; va3 &= ~w33;
                        CLR_BIT(r3, va0, va1, va2, va3);
                    }
                }
            }
            skeep[c * WPC + 0] = k0;
            skeep[c * WPC + 1] = k1;
            skeep[c * WPC + 2] = k2;
            skeep[c * WPC + 3] = k3;
            knum = n;
        }
        __syncthreads();

        // propagation: 4 threads per word, 8 accumulators (MLP 32/word)
        {
            int w = (c + 1) * WPC + (t >> 2);
            int sub = t & 3;
            u64 a0 = 0, a1 = 0, a2 = 0, a3 = 0, a4 = 0, a5 = 0, a6 = 0, a7 = 0;
            if (w < NWv) {
                const u64* bp = g_mask + (size_t)(c * CH) * NW + w;
                int n = knum;
                int i = sub;
                for (; i + 28 < n; i += 32) {
                    a0 |= bp[(size_t)klist[i] * NW];
                    a1 |= bp[(size_t)klist[i + 4] * NW];
                    a2 |= bp[(size_t)klist[i + 8] * NW];
                    a3 |= bp[(size_t)klist[i + 12] * NW];
                    a4 |= bp[(size_t)klist[i + 16] * NW];
                    a5 |= bp[(size_t)klist[i + 20] * NW];
                    a6 |= bp[(size_t)klist[i + 24] * NW];
                    a7 |= bp[(size_t)klist[i + 28] * NW];
                }
                for (; i < n; i += 4) a0 |= bp[(size_t)klist[i] * NW];
            }
            part[t] = ((a0 | a1) | (a2 | a3)) | ((a4 | a5) | (a6 | a7));
        }
        __syncthreads();
    }

    // fused masked output
    for (int j = t; j < M; j += 512) {
        if (j < V) {
            float f = ((skeep[j >> 6] >> (j & 63)) & 1ull) ? 1.0f : 0.0f;
#pragma unroll
            for (int c5 = 0; c5 < 5; c5++)
                out[j * 5 + c5] = g_ds[j * 5 + c5] * f;
        } else {
#pragma unroll
            for (int c5 = 0; c5 < 5; c5++)
                out[j * 5 + c5] = 0.0f;
        }
    }
}

// ---------------- launcher ---------------------------------------------------
extern "C" void kernel_launch(void* const* d_in, const int* in_sizes, int n_in,
                              void* d_out, int out_size) {
    const float* det = (const float*)d_in[0];
    const float* off = (const float*)d_in[1];
    const float* scl = (const float*)d_in[2];
    const float* bnd = (const float*)d_in[3];
    float* out = (float*)d_out;

    prep_kernel<<<32, 256>>>(det, off, scl, bnd);
    lsort_kernel<<<NTILE, 1024>>>();
    gmerge_kernel<<<8, 512>>>(4096, 2048);      // k=4096 global stage
    lmerge_kernel<4096, false><<<NTILE, 1024>>>();
    gmerge_kernel<<<8, 512>>>(8192, 4096);      // k=8192 global stages
    gmerge_kernel<<<8, 512>>>(8192, 2048);
    lmerge_kernel<8192, true><<<NTILE, 1024>>>();
    mask_kernel<<<dim3(NW, 32), 256>>>();
    scan_kernel<<<1, 512>>>(out);
}

// round 13
// speedup vs baseline: 1.1204x; 1.1204x over previous
#include <cuda_runtime.h>
#include <cstdint>

#define M 8192
#define NW 128          // 64-bit words per row (M/64)
#define NMS_T 0.3f
#define CH 256          // scan chunk size (elements)
#define WPC 4           // words per chunk (CH/64)
#define TILE 2048       // sort tile size
#define NTILE 4         // number of sort tiles (M/TILE)

typedef unsigned long long u64;

// ---------------- device scratch (no runtime allocation allowed) ------------
__device__ float  g_d[M * 5];        // transformed detections (orig order)
__device__ u64    g_ckey[M];         // packed (key<<13 | idx), padded to 8192
__device__ int    g_cnt;             // valid count (atomic; reset by scan)
__device__ int    g_V;               // valid count (published by lsort)
__device__ float  g_ds[M * 5];       // sorted detections (first V rows)
__device__ float4 g_boxes[M];        // x1,y1,x2,y2 (sorted order, first V)
__device__ u64    g_mask[M * NW];    // suppression bitmask (i>j bits only)

// ---------------- kernel 1: transform + score + compact (coalesced) ---------
__global__ void __launch_bounds__(256)
prep_kernel(const float* __restrict__ det, const float* __restrict__ off,
            const float* __restrict__ scl, const float* __restrict__ bnd) {
    __shared__ float srow[256 * 5];
    int b = blockIdx.x;                    // 32 blocks x 256 rows
    int tid = threadIdx.x;
    int lane = tid & 31;
    const float* src = det + b * 256 * 5;
    for (int i = tid; i < 256 * 5; i += 256) srow[i] = src[i];
    __syncthreads();

    int i = b * 256 + tid;                 // global row
    int w = i >> 10;
    float a0 = srow[tid * 5 + 0], a1 = srow[tid * 5 + 1], a2 = srow[tid * 5 + 2];
    float a3 = srow[tid * 5 + 3], a4 = srow[tid * 5 + 4];
    float d0 = off[w * 5 + 0] + a0 * scl[w * 5 + 0];
    float d1 = off[w * 5 + 1] + a1 * scl[w * 5 + 1];
    float d2 = off[w * 5 + 2] + a2 * scl[w * 5 + 2];
    float d3 = off[w * 5 + 3] + a3 * scl[w * 5 + 3];
    float d4 = off[w * 5 + 4] + a4 * scl[w * 5 + 4];
    bool valid = (a1 < bnd[w * 4 + 1]) && (a1 > bnd[w * 4 + 0]) &&
                 (a2 < bnd[w * 4 + 3]) && (a2 > bnd[w * 4 + 2]);

    g_d[i * 5 + 0] = d0;
    g_d[i * 5 + 1] = d1;
    g_d[i * 5 + 2] = d2;
    g_d[i * 5 + 3] = d3;
    g_d[i * 5 + 4] = d4;

    bool take = valid && d0 > 0.0f;        // non-positive scores -> zero rows
    unsigned ball = __ballot_sync(0xffffffffu, take);
    if (ball) {
        int nb = __popc(ball);
        int leader = __ffs(ball) - 1;
        int base = 0;
        if (lane == leader) base = atomicAdd(&g_cnt, nb);
        base = __shfl_sync(0xffffffffu, base, leader);
        if (take) {
            int o = __popc(ball & ((1u << lane) - 1));
            unsigned key = ~(__float_as_uint(d0) | 0x80000000u);
            g_ckey[base + o] = ((u64)key << 13) | (u64)i;  // (score desc, idx asc)
        }
    }
}

// ---------------- kernel 2a: local bitonic sort of 2048-tiles ---------------
__global__ void __launch_bounds__(1024) lsort_kernel() {
    __shared__ u64 sv[TILE];
    int tb = blockIdx.x << 11;
    int tid = threadIdx.x;
    int V = g_cnt;
    if (tb == 0 && tid == 0) g_V = V;

    if (tb >= V) {                         // pure padding tile: just materialize
        g_ckey[tb + tid] = ~0ull;
        g_ckey[tb + tid + 1024] = ~0ull;
        return;
    }

    u64 r0 = (tb + tid < V) ? g_ckey[tb + tid] : ~0ull;
    u64 r1 = (tb + tid + 1024 < V) ? g_ckey[tb + tid + 1024] : ~0ull;

    // phase A: k = 2..32 entirely in registers (intra-warp shuffles)
    int e0 = tb + tid, e1 = tb + 1024 + tid;
#pragma unroll
    for (int k = 2; k <= 32; k <<= 1) {
#pragma unroll
        for (int s = k >> 1; s >= 1; s >>= 1) {
            u64 o0 = __shfl_xor_sync(0xffffffffu, r0, s);
            u64 o1 = __shfl_xor_sync(0xffffffffu, r1, s);
            bool m0 = (((e0 & s) == 0) == ((e0 & k) == 0));
            bool m1 = (((e1 & s) == 0) == ((e1 & k) == 0));
            r0 = ((r0 < o0) == m0) ? r0 : o0;
            r1 = ((r1 < o1) == m1) ? r1 : o1;
        }
    }
    sv[tid] = r0;
    sv[tid + 1024] = r1;
    __syncthreads();

    // phase B: k = 64..2048 (strides >=32 in smem, <=16 via shuffles)
#pragma unroll
    for (int k = 64; k <= TILE; k <<= 1) {
        for (int s = k >> 1; s >= 32; s >>= 1) {
            int a = ((tid & ~(s - 1)) << 1) | (tid & (s - 1));
            bool up = (((tb + a) & k) == 0);
            u64 x = sv[a], y = sv[a + s];
            if ((x > y) == up) { sv[a] = y; sv[a + s] = x; }
            __syncthreads();
        }
        r0 = sv[tid];
        r1 = sv[tid + 1024];
#pragma unroll
        for (int s = 16; s >= 1; s >>= 1) {
            u64 o0 = __shfl_xor_sync(0xffffffffu, r0, s);
            u64 o1 = __shfl_xor_sync(0xffffffffu, r1, s);
            bool m0 = (((e0 & s) == 0) == ((e0 & k) == 0));
            bool m1 = (((e1 & s) == 0) == ((e1 & k) == 0));
            r0 = ((r0 < o0) == m0) ? r0 : o0;
            r1 = ((r1 < o1) == m1) ? r1 : o1;
        }
        if (k < TILE) {
            sv[tid] = r0;
            sv[tid + 1024] = r1;
            __syncthreads();
        }
    }
    g_ckey[tb + tid] = r0;
    g_ckey[tb + 1024 + tid] = r1;
}

// ---------------- kernel 2b: full k=4096 phase per 4096-half ----------------
__global__ void __launch_bounds__(1024) kphase4096_kernel() {
    __shared__ u64 sv[4096];
    int base = blockIdx.x << 12;
    int tid = threadIdx.x;
    int V = g_V;
    // V<=2048: halves already sorted/padding; base>=V: pure padding half
    if (V <= 2048 || base >= V) return;

#pragma unroll
    for (int i = 0; i < 4; i++) sv[tid + i * 1024] = g_ckey[base + tid + i * 1024];
    __syncthreads();

    bool up = ((base & 4096) == 0);        // uniform direction per block
    for (int s = 2048; s >= 32; s >>= 1) {
#pragma unroll
        for (int i = 0; i < 2; i++) {
            int v = tid + i * 1024;
            int a = ((v & ~(s - 1)) << 1) | (v & (s - 1));
            u64 x = sv[a], y = sv[a + s];
            if ((x > y) == up) { sv[a] = y; sv[a + s] = x; }
        }
        __syncthreads();
    }
    u64 r0 = sv[tid], r1 = sv[tid + 1024], r2 = sv[tid + 2048], r3 = sv[tid + 3072];
#pragma unroll
    for (int s = 16; s >= 1; s >>= 1) {
        u64 o0 = __shfl_xor_sync(0xffffffffu, r0, s);
        u64 o1 = __shfl_xor_sync(0xffffffffu, r1, s);
        u64 o2 = __shfl_xor_sync(0xffffffffu, r2, s);
        u64 o3 = __shfl_xor_sync(0xffffffffu, r3, s);
        bool m = (((tid & s) == 0) == up);  // low bits of element == low bits of tid
        r0 = ((r0 < o0) == m) ? r0 : o0;
        r1 = ((r1 < o1) == m) ? r1 : o1;
        r2 = ((r2 < o2) == m) ? r2 : o2;
        r3 = ((r3 < o3) == m) ? r3 : o3;
    }
    g_ckey[base + tid] = r0;
    g_ckey[base + tid + 1024] = r1;
    g_ckey[base + tid + 2048] = r2;
    g_ckey[base + tid + 3072] = r3;
}

// ---------------- kernel 2c: full k=8192 phase + fused gather ---------------
extern "C" __global__ void __launch_bounds__(1024) kphase8192_kernel() {
    extern __shared__ u64 sv8[];           // 64KB dynamic
    int tid = threadIdx.x;
    int V = g_V;

    if (V > 4096) {
        // run the whole k=8192 merge phase in one block
#pragma unroll
        for (int i = 0; i < 8; i++) sv8[tid + i * 1024] = g_ckey[tid + i * 1024];
        __syncthreads();
        for (int s = 4096; s >= 32; s >>= 1) {
#pragma unroll
            for (int i = 0; i < 4; i++) {
                int v = tid + i * 1024;
                int a = ((v & ~(s - 1)) << 1) | (v & (s - 1));
                u64 x = sv8[a], y = sv8[a + s];
                if (x > y) { sv8[a] = y; sv8[a + s] = x; }   // up = true globally
            }
            __syncthreads();
        }
        u64 r[8];
#pragma unroll
        for (int i = 0; i < 8; i++) r[i] = sv8[tid + i * 1024];
#pragma unroll
        for (int s = 16; s >= 1; s >>= 1) {
            bool m = ((tid & s) == 0);
#pragma unroll
            for (int i = 0; i < 8; i++) {
                u64 o = __shfl_xor_sync(0xffffffffu, r[i], s);
                r[i] = ((r[i] < o) == m) ? r[i] : o;
            }
        }
#pragma unroll
        for (int i = 0; i < 8; i++) sv8[tid + i * 1024] = r[i];
        __syncthreads();
        for (int j = tid; j < V; j += 1024) {
            int idx = (int)(sv8[j] & 0x1FFFu);
            float dd[5];
#pragma unroll
            for (int c = 0; c < 5; c++) {
                dd[c] = g_d[idx * 5 + c];
                g_ds[j * 5 + c] = dd[c];
            }
            g_boxes[j] = make_float4(dd[1] - 0.5f * dd[3], dd[2] - 0.5f * dd[4],
                                     dd[1] + 0.5f * dd[3], dd[2] + 0.5f * dd[4]);
        }
    } else {
        // V <= 4096: first 4096 slots already fully ascending; gather directly
        for (int j = tid; j < V; j += 1024) {
            int idx = (int)(g_ckey[j] & 0x1FFFu);
            float dd[5];
#pragma unroll
            for (int c = 0; c < 5; c++) {
                dd[c] = g_d[idx * 5 + c];
                g_ds[j * 5 + c] = dd[c];
            }
            g_boxes[j] = make_float4(dd[1] - 0.5f * dd[3], dd[2] - 0.5f * dd[4],
                                     dd[1] + 0.5f * dd[3], dd[2] + 0.5f * dd[4]);
        }
    }
}

// ---------------- kernel 3: IoU bitmask (256 rows x 64 cols per block) ------
__global__ void __launch_bounds__(256) mask_kernel() {
    int bx = blockIdx.x;                       // column word 0..127
    int by = blockIdx.y;                       // row tile 0..31 (256 rows each)
    int V = g_V;
    if ((by << 8) >= V || (bx << 6) >= V) return;
    if (bx < (by << 2)) return;                // tile entirely i <= j

    __shared__ float4 cbox[64];
    __shared__ float  carea[64];
    int t = threadIdx.x;
    if (t < 64) {
        int ci = (bx << 6) + t;
        float4 cb = (ci < V) ? g_boxes[ci] : make_float4(0.f, 0.f, 0.f, 0.f);
        cbox[t] = cb;
        carea[t] = fmaxf(cb.z - cb.x, 0.f) * fmaxf(cb.w - cb.y, 0.f);
    }
    __syncthreads();

    int j = (by << 8) + t;
    if (j >= V) return;
    float4 rb = g_boxes[j];
    float  ra = fmaxf(rb.z - rb.x, 0.f) * fmaxf(rb.w - rb.y, 0.f);

    u64 bits = 0ull;
#pragma unroll
    for (int b = 0; b < 64; b++) {
        int i = (bx << 6) + b;
        if (i > j) {
            float iw = fmaxf(fminf(rb.z, cbox[b].z) - fmaxf(rb.x, cbox[b].x), 0.f);
            float ih = fmaxf(fminf(rb.w, cbox[b].w) - fmaxf(rb.y, cbox[b].y), 0.f);
            float inter = iw * ih;
            float uni = ra + carea[b] - inter;
            if (inter > NMS_T * fmaxf(uni, 1e-9f)) bits |= (1ull << b);
        }
    }
    g_mask[(size_t)j * NW + bx] = bits;
}

// ---------------- kernel 4: greedy NMS scan (R8 exact) + fused output -------
__global__ void __launch_bounds__(512) scan_kernel(float* __restrict__ out) {
    __shared__ u64 remv[NW];
    __shared__ u64 skeep[NW];
    __shared__ u64 sdiag[CH][WPC];        // 8KB diagonal block
    __shared__ u64 part[512];
    __shared__ unsigned short klist[CH];
    __shared__ int knum;
    int t = threadIdx.x;
    int V = g_V;
    int NC = (V + CH - 1) / CH;
    int NWv = (V + 63) >> 6;

    if (t == 511) g_cnt = 0;              // deterministic reset for next replay
    if (t < NW) { remv[t] = 0ull; skeep[t] = 0ull; }
    part[t] = 0ull;

    // prefetch diag block of chunk 0 (row = i>>2, word = i&3)
    u64 d0 = 0ull, d1 = 0ull;
    if (NC > 0) {
        d0 = g_mask[(size_t)(t >> 2) * NW + (t & 3)];
        d1 = g_mask[(size_t)((t + 512) >> 2) * NW + ((t + 512) & 3)];
    }
    __syncthreads();

    for (int c = 0; c < NC; c++) {
        sdiag[t >> 2][t & 3] = d0;
        sdiag[(t + 512) >> 2][(t + 512) & 3] = d1;
        // fold prev chunk's propagation partials into remv (word c*WPC + t)
        if (t < NW) {
            int w = c * WPC + t;
            if (w < NW)
                remv[w] |= (part[t * 4] | part[t * 4 + 1]) |
                           (part[t * 4 + 2] | part[t * 4 + 3]);
        }
        __syncthreads();

        // prefetch next chunk's diag block
        if (c + 1 < NC) {
            int base = (c + 1) * CH;
            d0 = g_mask[(size_t)(base + (t >> 2)) * NW + ((c + 1) * WPC + (t & 3))];
            d1 = g_mask[(size_t)(base + ((t + 512) >> 2)) * NW +
                        ((c + 1) * WPC + ((t + 512) & 3))];
        }

        if (t == 0) {
            // simple greedy: EXACT R4/R8 loop (spill-sensitive, do not touch)
            u64 alive[WPC], kept[WPC];
#pragma unroll
            for (int u = 0; u < WPC; u++) {
                int rb = V - ((c * WPC + u) << 6);
                u64 vm = (rb >= 64) ? ~0ull : (rb <= 0 ? 0ull : ((1ull << rb) - 1ull));
                alive[u] = ~remv[c * WPC + u] & vm;
                kept[u] = 0ull;
            }
            int n = 0;
            for (int w = 0; w < WPC; w++) {
                while (alive[w]) {
                    int b = __ffsll((long long)alive[w]) - 1;
                    int rr = (w << 6) + b;
                    kept[w] |= 1ull << b;
                    klist[n++] = (unsigned short)rr;
                    alive[w] &= ~(1ull << b);
                    for (int u = w; u < WPC; u++)
                        alive[u] &= ~sdiag[rr][u];
                }
            }
#pragma unroll
            for (int u = 0; u < WPC; u++) skeep[c * WPC + u] = kept[u];
            knum = n;
        }
        __syncthreads();

        // propagation: 4 threads per word, 4 accumulators (MLP 16/word)
        {
            int w = (c + 1) * WPC + (t >> 2);
            int sub = t & 3;
            u64 a0 = 0ull, a1 = 0ull, a2 = 0ull, a3 = 0ull;
            if (w < NWv) {
                const u64* bp = g_mask + (size_t)(c * CH) * NW + w;
                int n = knum;
                int i = sub;
                for (; i + 12 < n; i += 16) {
                    a0 |= bp[(size_t)klist[i] * NW];
                    a1 |= bp[(size_t)klist[i + 4] * NW];
                    a2 |= bp[(size_t)klist[i + 8] * NW];
                    a3 |= bp[(size_t)klist[i + 12] * NW];
                }
                for (; i < n; i += 4) a0 |= bp[(size_t)klist[i] * NW];
            }
            part[t] = (a0 | a1) | (a2 | a3);
        }
        __syncthreads();
    }

    // fused masked output
    for (int j = t; j < M; j += 512) {
        if (j < V) {
            float f = ((skeep[j >> 6] >> (j & 63)) & 1ull) ? 1.0f : 0.0f;
#pragma unroll
            for (int c5 = 0; c5 < 5; c5++)
                out[j * 5 + c5] = g_ds[j * 5 + c5] * f;
        } else {
#pragma unroll
            for (int c5 = 0; c5 < 5; c5++)
                out[j * 5 + c5] = 0.0f;
        }
    }
}

// ---------------- launcher ---------------------------------------------------
extern "C" void kernel_launch(void* const* d_in, const int* in_sizes, int n_in,
                              void* d_out, int out_size) {
    const float* det = (const float*)d_in[0];
    const float* off = (const float*)d_in[1];
    const float* scl = (const float*)d_in[2];
    const float* bnd = (const float*)d_in[3];
    float* out = (float*)d_out;

    cudaFuncSetAttribute((const void*)kphase8192_kernel,
                         cudaFuncAttributeMaxDynamicSharedMemorySize, 65536);

    prep_kernel<<<32, 256>>>(det, off, scl, bnd);
    lsort_kernel<<<NTILE, 1024>>>();
    kphase4096_kernel<<<2, 1024>>>();
    kphase8192_kernel<<<1, 1024, 65536>>>();
    mask_kernel<<<dim3(NW, 32), 256>>>();
    scan_kernel<<<1, 512>>>(out);
}

// round 14
// speedup vs baseline: 1.2388x; 1.1057x over previous
#include <cuda_runtime.h>
#include <cstdint>

#define M 8192
#define NW 128          // 64-bit words per row (M/64)
#define NMS_T 0.3f
#define CH 256          // scan chunk size (elements)
#define WPC 4           // words per chunk (CH/64)
#define TILE 2048       // sort tile size
#define NTILE 4         // number of sort tiles (M/TILE)

typedef unsigned long long u64;

// ---------------- device scratch (no runtime allocation allowed) ------------
__device__ float  g_d[M * 5];        // transformed detections (orig order)
__device__ u64    g_ckey[M];         // packed (key<<13 | idx), padded to 8192
__device__ int    g_cnt;             // valid count (atomic; reset by scan)
__device__ int    g_V;               // valid count (published by lsort)
__device__ float  g_ds[M * 5];       // sorted detections (first V rows)
__device__ float4 g_boxes[M];        // x1,y1,x2,y2 (sorted order, first V)
__device__ u64    g_mask[M * NW];    // suppression bitmask (i>j bits only)

// ---------------- kernel 1: transform + score + compact (coalesced) ---------
__global__ void __launch_bounds__(256)
prep_kernel(const float* __restrict__ det, const float* __restrict__ off,
            const float* __restrict__ scl, const float* __restrict__ bnd) {
    __shared__ float srow[256 * 5];
    int b = blockIdx.x;                    // 32 blocks x 256 rows
    int tid = threadIdx.x;
    int lane = tid & 31;
    const float* src = det + b * 256 * 5;
    for (int i = tid; i < 256 * 5; i += 256) srow[i] = src[i];
    __syncthreads();

    int i = b * 256 + tid;                 // global row
    int w = i >> 10;
    float a0 = srow[tid * 5 + 0], a1 = srow[tid * 5 + 1], a2 = srow[tid * 5 + 2];
    float a3 = srow[tid * 5 + 3], a4 = srow[tid * 5 + 4];
    float d0 = off[w * 5 + 0] + a0 * scl[w * 5 + 0];
    float d1 = off[w * 5 + 1] + a1 * scl[w * 5 + 1];
    float d2 = off[w * 5 + 2] + a2 * scl[w * 5 + 2];
    float d3 = off[w * 5 + 3] + a3 * scl[w * 5 + 3];
    float d4 = off[w * 5 + 4] + a4 * scl[w * 5 + 4];
    bool valid = (a1 < bnd[w * 4 + 1]) && (a1 > bnd[w * 4 + 0]) &&
                 (a2 < bnd[w * 4 + 3]) && (a2 > bnd[w * 4 + 2]);

    g_d[i * 5 + 0] = d0;
    g_d[i * 5 + 1] = d1;
    g_d[i * 5 + 2] = d2;
    g_d[i * 5 + 3] = d3;
    g_d[i * 5 + 4] = d4;

    bool take = valid && d0 > 0.0f;        // non-positive scores -> zero rows
    unsigned ball = __ballot_sync(0xffffffffu, take);
    if (ball) {
        int nb = __popc(ball);
        int leader = __ffs(ball) - 1;
        int base = 0;
        if (lane == leader) base = atomicAdd(&g_cnt, nb);
        base = __shfl_sync(0xffffffffu, base, leader);
        if (take) {
            int o = __popc(ball & ((1u << lane) - 1));
            unsigned key = ~(__float_as_uint(d0) | 0x80000000u);
            g_ckey[base + o] = ((u64)key << 13) | (u64)i;  // (score desc, idx asc)
        }
    }
}

// ---------------- kernel 2a: local bitonic sort of 2048-tiles ---------------
__global__ void __launch_bounds__(1024) lsort_kernel() {
    __shared__ u64 sv[TILE];
    int tb = blockIdx.x << 11;
    int tid = threadIdx.x;
    int V = g_cnt;
    if (tb == 0 && tid == 0) g_V = V;

    if (tb >= V) {                         // pure padding tile: just materialize
        g_ckey[tb + tid] = ~0ull;
        g_ckey[tb + tid + 1024] = ~0ull;
        return;
    }

    u64 r0 = (tb + tid < V) ? g_ckey[tb + tid] : ~0ull;
    u64 r1 = (tb + tid + 1024 < V) ? g_ckey[tb + tid + 1024] : ~0ull;

    // phase A: k = 2..32 entirely in registers (intra-warp shuffles)
    int e0 = tb + tid, e1 = tb + 1024 + tid;
#pragma unroll
    for (int k = 2; k <= 32; k <<= 1) {
#pragma unroll
        for (int s = k >> 1; s >= 1; s >>= 1) {
            u64 o0 = __shfl_xor_sync(0xffffffffu, r0, s);
            u64 o1 = __shfl_xor_sync(0xffffffffu, r1, s);
            bool m0 = (((e0 & s) == 0) == ((e0 & k) == 0));
            bool m1 = (((e1 & s) == 0) == ((e1 & k) == 0));
            r0 = ((r0 < o0) == m0) ? r0 : o0;
            r1 = ((r1 < o1) == m1) ? r1 : o1;
        }
    }
    sv[tid] = r0;
    sv[tid + 1024] = r1;
    __syncthreads();

    // phase B: k = 64..2048 (strides >=32 in smem, <=16 via shuffles)
#pragma unroll
    for (int k = 64; k <= TILE; k <<= 1) {
        for (int s = k >> 1; s >= 32; s >>= 1) {
            int a = ((tid & ~(s - 1)) << 1) | (tid & (s - 1));
            bool up = (((tb + a) & k) == 0);
            u64 x = sv[a], y = sv[a + s];
            if ((x > y) == up) { sv[a] = y; sv[a + s] = x; }
            __syncthreads();
        }
        r0 = sv[tid];
        r1 = sv[tid + 1024];
#pragma unroll
        for (int s = 16; s >= 1; s >>= 1) {
            u64 o0 = __shfl_xor_sync(0xffffffffu, r0, s);
            u64 o1 = __shfl_xor_sync(0xffffffffu, r1, s);
            bool m0 = (((e0 & s) == 0) == ((e0 & k) == 0));
            bool m1 = (((e1 & s) == 0) == ((e1 & k) == 0));
            r0 = ((r0 < o0) == m0) ? r0 : o0;
            r1 = ((r1 < o1) == m1) ? r1 : o1;
        }
        if (k < TILE) {
            sv[tid] = r0;
            sv[tid + 1024] = r1;
            __syncthreads();
        }
    }
    g_ckey[tb + tid] = r0;
    g_ckey[tb + 1024 + tid] = r1;
}

// ---------------- kernel 2b: full k=4096 phase per 4096-half ----------------
__global__ void __launch_bounds__(1024) kphase4096_kernel() {
    __shared__ u64 sv[4096];
    int base = blockIdx.x << 12;
    int tid = threadIdx.x;
    int V = g_V;
    // V<=2048: halves already sorted/padding; base>=V: pure padding half
    if (V <= 2048 || base >= V) return;

#pragma unroll
    for (int i = 0; i < 4; i++) sv[tid + i * 1024] = g_ckey[base + tid + i * 1024];
    __syncthreads();

    bool up = ((base & 4096) == 0);        // uniform direction per block
    for (int s = 2048; s >= 32; s >>= 1) {
#pragma unroll
        for (int i = 0; i < 2; i++) {
            int v = tid + i * 1024;
            int a = ((v & ~(s - 1)) << 1) | (v & (s - 1));
            u64 x = sv[a], y = sv[a + s];
            if ((x > y) == up) { sv[a] = y; sv[a + s] = x; }
        }
        __syncthreads();
    }
    u64 r0 = sv[tid], r1 = sv[tid + 1024], r2 = sv[tid + 2048], r3 = sv[tid + 3072];
#pragma unroll
    for (int s = 16; s >= 1; s >>= 1) {
        u64 o0 = __shfl_xor_sync(0xffffffffu, r0, s);
        u64 o1 = __shfl_xor_sync(0xffffffffu, r1, s);
        u64 o2 = __shfl_xor_sync(0xffffffffu, r2, s);
        u64 o3 = __shfl_xor_sync(0xffffffffu, r3, s);
        bool m = (((tid & s) == 0) == up);  // low bits of element == low bits of tid
        r0 = ((r0 < o0) == m) ? r0 : o0;
        r1 = ((r1 < o1) == m) ? r1 : o1;
        r2 = ((r2 < o2) == m) ? r2 : o2;
        r3 = ((r3 < o3) == m) ? r3 : o3;
    }
    g_ckey[base + tid] = r0;
    g_ckey[base + tid + 1024] = r1;
    g_ckey[base + tid + 2048] = r2;
    g_ckey[base + tid + 3072] = r3;
}

// ---------------- kernel 2c: full k=8192 merge phase (skipped if V<=4096) ---
extern "C" __global__ void __launch_bounds__(1024) kphase8192_kernel() {
    extern __shared__ u64 sv8[];           // 64KB dynamic
    int tid = threadIdx.x;
    int V = g_V;
    if (V <= 4096) return;                 // first 4096 already fully ascending

#pragma unroll
    for (int i = 0; i < 8; i++) sv8[tid + i * 1024] = g_ckey[tid + i * 1024];
    __syncthreads();
    for (int s = 4096; s >= 32; s >>= 1) {
#pragma unroll
        for (int i = 0; i < 4; i++) {
            int v = tid + i * 1024;
            int a = ((v & ~(s - 1)) << 1) | (v & (s - 1));
            u64 x = sv8[a], y = sv8[a + s];
            if (x > y) { sv8[a] = y; sv8[a + s] = x; }   // up = true globally
        }
        __syncthreads();
    }
    u64 r[8];
#pragma unroll
    for (int i = 0; i < 8; i++) r[i] = sv8[tid + i * 1024];
#pragma unroll
    for (int s = 16; s >= 1; s >>= 1) {
        bool m = ((tid & s) == 0);
#pragma unroll
        for (int i = 0; i < 8; i++) {
            u64 o = __shfl_xor_sync(0xffffffffu, r[i], s);
            r[i] = ((r[i] < o) == m) ? r[i] : o;
        }
    }
#pragma unroll
    for (int i = 0; i < 8; i++) g_ckey[tid + i * 1024] = r[i];
}

// ---------------- kernel 2d: multi-block gather (sorted rows + boxes) -------
__global__ void __launch_bounds__(256) gather_kernel() {
    int j = blockIdx.x * 256 + threadIdx.x;
    int V = g_V;
    if (j >= V) return;
    int idx = (int)(g_ckey[j] & 0x1FFFu);
    float dd[5];
#pragma unroll
    for (int c = 0; c < 5; c++) {
        dd[c] = g_d[idx * 5 + c];
        g_ds[j * 5 + c] = dd[c];
    }
    g_boxes[j] = make_float4(dd[1] - 0.5f * dd[3], dd[2] - 0.5f * dd[4],
                             dd[1] + 0.5f * dd[3], dd[2] + 0.5f * dd[4]);
}

// ---------------- kernel 3: IoU bitmask (256 rows x 64 cols per block) ------
__global__ void __launch_bounds__(256) mask_kernel() {
    int bx = blockIdx.x;                       // column word 0..127
    int by = blockIdx.y;                       // row tile 0..31 (256 rows each)
    int V = g_V;
    if ((by << 8) >= V || (bx << 6) >= V) return;
    if (bx < (by << 2)) return;                // tile entirely i <= j

    __shared__ float4 cbox[64];
    __shared__ float  carea[64];
    int t = threadIdx.x;
    if (t < 64) {
        int ci = (bx << 6) + t;
        float4 cb = (ci < V) ? g_boxes[ci] : make_float4(0.f, 0.f, 0.f, 0.f);
        cbox[t] = cb;
        carea[t] = fmaxf(cb.z - cb.x, 0.f) * fmaxf(cb.w - cb.y, 0.f);
    }
    __syncthreads();

    int j = (by << 8) + t;
    if (j >= V) return;
    float4 rb = g_boxes[j];
    float  ra = fmaxf(rb.z - rb.x, 0.f) * fmaxf(rb.w - rb.y, 0.f);

    u64 bits = 0ull;
#pragma unroll
    for (int b = 0; b < 64; b++) {
        int i = (bx << 6) + b;
        if (i > j) {
            float iw = fmaxf(fminf(rb.z, cbox[b].z) - fmaxf(rb.x, cbox[b].x), 0.f);
            float ih = fmaxf(fminf(rb.w, cbox[b].w) - fmaxf(rb.y, cbox[b].y), 0.f);
            float inter = iw * ih;
            float uni = ra + carea[b] - inter;
            if (inter > NMS_T * fmaxf(uni, 1e-9f)) bits |= (1ull << b);
        }
    }
    g_mask[(size_t)j * NW + bx] = bits;
}

// ---------------- kernel 4: greedy NMS scan (R8 exact) + fused output -------
__global__ void __launch_bounds__(512) scan_kernel(float* __restrict__ out) {
    __shared__ u64 remv[NW];
    __shared__ u64 skeep[NW];
    __shared__ u64 sdiag[CH][WPC];        // 8KB diagonal block
    __shared__ u64 part[512];
    __shared__ unsigned short klist[CH];
    __shared__ int knum;
    int t = threadIdx.x;
    int V = g_V;
    int NC = (V + CH - 1) / CH;
    int NWv = (V + 63) >> 6;

    if (t == 511) g_cnt = 0;              // deterministic reset for next replay
    if (t < NW) { remv[t] = 0ull; skeep[t] = 0ull; }
    part[t] = 0ull;

    // prefetch diag block of chunk 0 (row = i>>2, word = i&3)
    u64 d0 = 0ull, d1 = 0ull;
    if (NC > 0) {
        d0 = g_mask[(size_t)(t >> 2) * NW + (t & 3)];
        d1 = g_mask[(size_t)((t + 512) >> 2) * NW + ((t + 512) & 3)];
    }
    __syncthreads();

    for (int c = 0; c < NC; c++) {
        sdiag[t >> 2][t & 3] = d0;
        sdiag[(t + 512) >> 2][(t + 512) & 3] = d1;
        // fold prev chunk's propagation partials into remv (word c*WPC + t)
        if (t < NW) {
            int w = c * WPC + t;
            if (w < NW)
                remv[w] |= (part[t * 4] | part[t * 4 + 1]) |
                           (part[t * 4 + 2] | part[t * 4 + 3]);
        }
        __syncthreads();

        // prefetch next chunk's diag block
        if (c + 1 < NC) {
            int base = (c + 1) * CH;
            d0 = g_mask[(size_t)(base + (t >> 2)) * NW + ((c + 1) * WPC + (t & 3))];
            d1 = g_mask[(size_t)(base + ((t + 512) >> 2)) * NW +
                        ((c + 1) * WPC + ((t + 512) & 3))];
        }

        if (t == 0) {
            // simple greedy: EXACT R4/R8 loop (spill-sensitive, do not touch)
            u64 alive[WPC], kept[WPC];
#pragma unroll
            for (int u = 0; u < WPC; u++) {
                int rb = V - ((c * WPC + u) << 6);
                u64 vm = (rb >= 64) ? ~0ull : (rb <= 0 ? 0ull : ((1ull << rb) - 1ull));
                alive[u] = ~remv[c * WPC + u] & vm;
                kept[u] = 0ull;
            }
            int n = 0;
            for (int w = 0; w < WPC; w++) {
                while (alive[w]) {
                    int b = __ffsll((long long)alive[w]) - 1;
                    int rr = (w << 6) + b;
                    kept[w] |= 1ull << b;
                    klist[n++] = (unsigned short)rr;
                    alive[w] &= ~(1ull << b);
                    for (int u = w; u < WPC; u++)
                        alive[u] &= ~sdiag[rr][u];
                }
            }
#pragma unroll
            for (int u = 0; u < WPC; u++) skeep[c * WPC + u] = kept[u];
            knum = n;
        }
        __syncthreads();

        // propagation: 4 threads per word, 4 accumulators (MLP 16/word)
        {
            int w = (c + 1) * WPC + (t >> 2);
            int sub = t & 3;
            u64 a0 = 0ull, a1 = 0ull, a2 = 0ull, a3 = 0ull;
            if (w < NWv) {
                const u64* bp = g_mask + (size_t)(c * CH) * NW + w;
                int n = knum;
                int i = sub;
                for (; i + 12 < n; i += 16) {
                    a0 |= bp[(size_t)klist[i] * NW];
                    a1 |= bp[(size_t)klist[i + 4] * NW];
                    a2 |= bp[(size_t)klist[i + 8] * NW];
                    a3 |= bp[(size_t)klist[i + 12] * NW];
                }
                for (; i < n; i += 4) a0 |= bp[(size_t)klist[i] * NW];
            }
            part[t] = (a0 | a1) | (a2 | a3);
        }
        __syncthreads();
    }

    // fused masked output
    for (int j = t; j < M; j += 512) {
        if (j < V) {
            float f = ((skeep[j >> 6] >> (j & 63)) & 1ull) ? 1.0f : 0.0f;
#pragma unroll
            for (int c5 = 0; c5 < 5; c5++)
                out[j * 5 + c5] = g_ds[j * 5 + c5] * f;
        } else {
#pragma unroll
            for (int c5 = 0; c5 < 5; c5++)
                out[j * 5 + c5] = 0.0f;
        }
    }
}

// ---------------- launcher ---------------------------------------------------
extern "C" void kernel_launch(void* const* d_in, const int* in_sizes, int n_in,
                              void* d_out, int out_size) {
    const float* det = (const float*)d_in[0];
    const float* off = (const float*)d_in[1];
    const float* scl = (const float*)d_in[2];
    const float* bnd = (const float*)d_in[3];
    float* out = (float*)d_out;

    cudaFuncSetAttribute((const void*)kphase8192_kernel,
                         cudaFuncAttributeMaxDynamicSharedMemorySize, 65536);

    prep_kernel<<<32, 256>>>(det, off, scl, bnd);
    lsort_kernel<<<NTILE, 1024>>>();
    kphase4096_kernel<<<2, 1024>>>();
    kphase8192_kernel<<<1, 1024, 65536>>>();
    gather_kernel<<<32, 256>>>();
    mask_kernel<<<dim3(NW, 32), 256>>>();
    scan_kernel<<<1, 512>>>(out);
}